// round 2
// baseline (speedup 1.0000x reference)
#include <cuda_runtime.h>
#include <math.h>

#define FEAT_IN 64
#define EMB     256
#define KTOP    30
#define BATCH   48
#define NGR     11
#define GG      528        // BATCH*NGR
#define NPG     192
#define EPG     384
#define NN      (GG*NPG)   // 101376
#define EE      (GG*EPG)   // 202752
#define DD      769        // 3*EMB+1
#define DENSE   2816       // 11*EMB
#define KIN     (NGR*DENSE) // 30976

// ---------------- scratch (device globals: no allocation allowed) ----------------
__device__ float g_dis[NN];
__device__ float g_h[(long)NN*EMB];
__device__ float g_x1[(long)NN*EMB];
__device__ float g_x2[(long)NN*EMB];
__device__ float g_x3[(long)NN*EMB];
__device__ float g_h4[NN];
__device__ float g_x4[NN];
__device__ int   g_sel[GG*KTOP];
__device__ float g_xsel[(long)GG*KTOP*DD];
__device__ float g_y5[(long)GG*KTOP*128];
__device__ float g_y2[(long)GG*15*128];
__device__ float g_y3[(long)GG*11*EMB];
__device__ float g_emb[(long)BATCH*KIN];
__device__ float g_hd[BATCH*EMB];
__device__ float g_w5t[(long)DD*128];
__device__ float g_w6t[(long)640*EMB];

// ---------------- degree / dis ----------------
__global__ void deg_init_k() {
    int i = blockIdx.x*256 + threadIdx.x;
    if (i < NN) g_dis[i] = 1.0f;
}
__global__ void deg_cnt_k(const int* __restrict__ dst) {
    int e = blockIdx.x*256 + threadIdx.x;
    if (e < EE) atomicAdd(&g_dis[dst[e]], 1.0f);
}
__global__ void deg_fin_k() {
    int i = blockIdx.x*256 + threadIdx.x;
    if (i < NN) g_dis[i] = rsqrtf(g_dis[i]);
}

// ---------------- weight reshapes ----------------
__global__ void tw5_k(const float* __restrict__ w5) {
    int i = blockIdx.x*256 + threadIdx.x;
    if (i < 128*DD) {
        int oc = i / DD, d = i % DD;
        g_w5t[(long)d*128 + oc] = w5[i];
    }
}
__global__ void tw6_k(const float* __restrict__ w6) {
    int i = blockIdx.x*256 + threadIdx.x;
    if (i < 256*640) {
        int oc = i / 640, rem = i % 640;
        int ic = rem / 5, j = rem % 5;
        g_w6t[(long)(j*128 + ic)*256 + oc] = w6[i];
    }
}

// ---------------- generic tiled SGEMM: C = A[M,K] @ B[K,Nc] (+bias, relu) ----------------
// mode 0: A row-major lda=K.  mode 1: conv6 row mapping (row r -> base 128*(r + 4*(r/11))).
#define BM 128
#define BN 64
#define BKK 16
__global__ void gemm_k(const float* __restrict__ A, const float* __restrict__ B,
                       const float* __restrict__ bias, float* __restrict__ C,
                       int M, int K, int Nc, int relu, int mode)
{
    __shared__ __align__(16) float As[BKK][BM+4];
    __shared__ __align__(16) float Bs[BKK][BN];
    int tid = threadIdx.x;
    int tx = tid & 15;        // 16 -> 64 cols / 4
    int ty = tid >> 4;        // 16 -> 128 rows / 8
    int row0 = blockIdx.y * BM;
    int col0 = blockIdx.x * BN;
    float acc[8][4];
    #pragma unroll
    for (int i = 0; i < 8; i++)
        #pragma unroll
        for (int j = 0; j < 4; j++) acc[i][j] = 0.f;

    for (int k0 = 0; k0 < K; k0 += BKK) {
        #pragma unroll
        for (int q = 0; q < 8; q++) {
            int f = q*256 + tid;
            int m = f >> 4, kk = f & 15;
            int gm = row0 + m, gk = k0 + kk;
            float v = 0.f;
            if (gm < M && gk < K) {
                long base;
                if (mode == 0) base = (long)gm * K;
                else           base = (long)128 * (gm + 4*(gm/11));
                v = A[base + gk];
            }
            As[kk][m] = v;
        }
        #pragma unroll
        for (int q = 0; q < 4; q++) {
            int f = q*256 + tid;
            int kk = f >> 6, n = f & 63;
            int gk = k0 + kk;
            Bs[kk][n] = (gk < K) ? B[(long)gk*Nc + col0 + n] : 0.f;
        }
        __syncthreads();
        #pragma unroll
        for (int kk = 0; kk < BKK; kk++) {
            float4 a0 = *(const float4*)&As[kk][ty*8];
            float4 a1 = *(const float4*)&As[kk][ty*8+4];
            float4 bb = *(const float4*)&Bs[kk][tx*4];
            float a[8] = {a0.x,a0.y,a0.z,a0.w,a1.x,a1.y,a1.z,a1.w};
            float b[4] = {bb.x,bb.y,bb.z,bb.w};
            #pragma unroll
            for (int i = 0; i < 8; i++)
                #pragma unroll
                for (int j = 0; j < 4; j++)
                    acc[i][j] = fmaf(a[i], b[j], acc[i][j]);
        }
        __syncthreads();
    }
    #pragma unroll
    for (int i = 0; i < 8; i++) {
        int gm = row0 + ty*8 + i;
        if (gm >= M) continue;
        #pragma unroll
        for (int j = 0; j < 4; j++) {
            int gn = col0 + tx*4 + j;
            float v = acc[i][j];
            if (bias) v += bias[gn];
            if (relu) v = fmaxf(v, 0.f);
            C[(long)gm*Nc + gn] = v;
        }
    }
}

// ---------------- GCN aggregation: out = tanh(agg + h*dis^2 + b) ----------------
#define CCH 64
__global__ void gcn_agg_k(const float* __restrict__ h, const int* __restrict__ src,
                          const int* __restrict__ dst, const float* __restrict__ bias,
                          float* __restrict__ out)
{
    extern __shared__ float sm[];
    float* hs   = sm;                 // NPG*CCH
    float* as   = hs + NPG*CCH;       // NPG*CCH
    float* diss = as + NPG*CCH;       // NPG
    int*  srcl  = (int*)(diss + NPG); // EPG
    int*  dstl  = srcl + EPG;         // EPG
    int g = blockIdx.x >> 2;
    int chunk = blockIdx.x & 3;
    int tid = threadIdx.x;
    int c0 = chunk * CCH;

    for (int i = tid; i < NPG; i += 256) diss[i] = g_dis[g*NPG + i];
    for (int e = tid; e < EPG; e += 256) {
        srcl[e] = src[g*EPG + e] - g*NPG;
        dstl[e] = dst[g*EPG + e] - g*NPG;
    }
    __syncthreads();
    for (int f = tid; f < NPG*CCH; f += 256) {
        int node = f >> 6, c = f & 63;
        float v = h[(long)(g*NPG + node)*EMB + c0 + c];
        hs[f] = v;
        float d = diss[node];
        as[f] = v * d * d;
    }
    __syncthreads();
    int esub = tid >> 6, c = tid & 63;
    for (int e0 = 0; e0 < EPG; e0 += 4) {
        int e = e0 + esub;
        int s = srcl[e], d = dstl[e];
        float coef = diss[s] * diss[d];
        atomicAdd(&as[d*CCH + c], hs[s*CCH + c] * coef);
    }
    __syncthreads();
    for (int f = tid; f < NPG*CCH; f += 256) {
        int node = f >> 6, c = f & 63;
        out[(long)(g*NPG + node)*EMB + c0 + c] = tanhf(as[f] + bias[c0 + c]);
    }
}

// ---------------- layer 4: GEMV + scalar GCN ----------------
__global__ void gemv4_k(const float* __restrict__ x3, const float* __restrict__ W4,
                        float* __restrict__ h4)
{
    int warp = (blockIdx.x*blockDim.x + threadIdx.x) >> 5;
    int lane = threadIdx.x & 31;
    if (warp >= NN) return;
    const float* row = x3 + (long)warp*EMB;
    float s = 0.f;
    #pragma unroll 4
    for (int c = lane; c < EMB; c += 32) s += row[c] * W4[c];
    #pragma unroll
    for (int o = 16; o > 0; o >>= 1) s += __shfl_down_sync(0xffffffffu, s, o);
    if (lane == 0) h4[warp] = s;
}

__global__ void gcn4_k(const float* __restrict__ h4, const int* __restrict__ src,
                       const int* __restrict__ dst, const float* __restrict__ b4,
                       float* __restrict__ x4out)
{
    __shared__ float hv[NPG], av[NPG], dv[NPG];
    int g = blockIdx.x, tid = threadIdx.x;
    for (int i = tid; i < NPG; i += 256) {
        float v = h4[g*NPG + i];
        float d = g_dis[g*NPG + i];
        hv[i] = v; dv[i] = d; av[i] = v*d*d;
    }
    __syncthreads();
    for (int e = tid; e < EPG; e += 256) {
        int s = src[g*EPG + e] - g*NPG;
        int d = dst[g*EPG + e] - g*NPG;
        atomicAdd(&av[d], hv[s]*dv[s]*dv[d]);
    }
    __syncthreads();
    float bb = b4[0];
    for (int i = tid; i < NPG; i += 256)
        x4out[g*NPG + i] = tanhf(av[i] + bb);
}

// ---------------- sort pooling: top-K by x4, descending, tie -> lower idx ----------------
__global__ void sortpool_k(const float* __restrict__ x4, int* __restrict__ sel)
{
    __shared__ float v[NPG];
    int g = blockIdx.x, t = threadIdx.x;  // 192 threads
    v[t] = x4[g*NPG + t];
    __syncthreads();
    float mv = v[t];
    int rank = 0;
    for (int j = 0; j < NPG; j++) {
        float o = v[j];
        rank += (o > mv) || (o == mv && j < t);
    }
    if (rank < KTOP) sel[g*KTOP + rank] = t;
}

// ---------------- gather selected node features into [G*K, 769] ----------------
__global__ void gather_k(const int* __restrict__ sel, float* __restrict__ xsel)
{
    int r = blockIdx.x;             // 0..G*K-1
    int g = r / KTOP;
    long node = (long)g*NPG + sel[r];
    float* o = xsel + (long)r*DD;
    int t = threadIdx.x;            // 256
    o[t]        = g_x1[node*EMB + t];
    o[256 + t]  = g_x2[node*EMB + t];
    o[512 + t]  = g_x3[node*EMB + t];
    if (t == 0) o[768] = g_x4[node];
}

// ---------------- maxpool pairs along K ----------------
__global__ void maxpool_k(const float* __restrict__ y5, float* __restrict__ y2)
{
    int idx = blockIdx.x*blockDim.x + threadIdx.x;
    if (idx >= GG*15*128) return;
    int oc = idx & 127;
    int p  = (idx >> 7) % 15;
    int g  = idx / (15*128);
    float a = y5[((long)g*KTOP + 2*p)*128 + oc];
    float b = y5[((long)g*KTOP + 2*p + 1)*128 + oc];
    y2[idx] = fmaxf(a, b);
}

// ---------------- emb reshape: y3[G,256,11] -> emb[B, 30976] ----------------
__global__ void embre_k(const float* __restrict__ y3, float* __restrict__ emb)
{
    int r = blockIdx.x;            // g*11 + t
    int oc = threadIdx.x;          // 256
    int g = r / 11, t = r % 11;
    int b = g / NGR, ng = g % NGR;
    emb[(long)b*KIN + ng*DENSE + oc*11 + t] = y3[(long)r*EMB + oc];
}

// ---------------- dense1: h = relu(emb @ Wc1 + bc1), [48,30976]x[30976,256] ----------------
__global__ void dense1_k(const float* __restrict__ emb, const float* __restrict__ Wc1,
                         const float* __restrict__ bc1, float* __restrict__ hd)
{
    int b = blockIdx.x, ch = blockIdx.y;
    int tid = threadIdx.x;
    int oc = ch*64 + (tid & 63);
    int s = tid >> 6;               // 4 k-slices
    const int SL = KIN / 4;         // 7744
    const float* arow = emb + (long)b*KIN;
    float acc = 0.f;
    int i0 = s*SL, i1 = i0 + SL;
    #pragma unroll 4
    for (int i = i0; i < i1; i++) acc += arow[i] * Wc1[(long)i*EMB + oc];
    __shared__ float red[256];
    red[tid] = acc;
    __syncthreads();
    if (s == 0) {
        float v = red[tid] + red[tid+64] + red[tid+128] + red[tid+192] + bc1[oc];
        hd[b*EMB + oc] = fmaxf(v, 0.f);
    }
}

// ---------------- dense2: logits = h @ Wc2 + bc2 ----------------
__global__ void dense2_k(const float* __restrict__ hd, const float* __restrict__ Wc2,
                         const float* __restrict__ bc2, float* __restrict__ out)
{
    int t = blockIdx.x*blockDim.x + threadIdx.x;
    if (t >= BATCH*10) return;
    int b = t / 10, o = t % 10;
    float s = bc2[o];
    #pragma unroll 8
    for (int k = 0; k < EMB; k++) s += hd[b*EMB + k] * Wc2[k*10 + o];
    out[t] = s;
}

// ---------------- launch ----------------
extern "C" void kernel_launch(void* const* d_in, const int* in_sizes, int n_in,
                              void* d_out, int out_size)
{
    const float* x   = (const float*)d_in[0];
    const int*   src = (const int*)d_in[1];
    const int*   dst = (const int*)d_in[2];
    const float* W1  = (const float*)d_in[3];
    const float* b1  = (const float*)d_in[4];
    const float* W2  = (const float*)d_in[5];
    const float* b2  = (const float*)d_in[6];
    const float* W3  = (const float*)d_in[7];
    const float* b3  = (const float*)d_in[8];
    const float* W4  = (const float*)d_in[9];
    const float* b4  = (const float*)d_in[10];
    const float* w5  = (const float*)d_in[11];
    const float* bc5 = (const float*)d_in[12];
    const float* w6  = (const float*)d_in[13];
    const float* bc6 = (const float*)d_in[14];
    const float* Wc1 = (const float*)d_in[15];
    const float* bc1 = (const float*)d_in[16];
    const float* Wc2 = (const float*)d_in[17];
    const float* bc2 = (const float*)d_in[18];
    float* out = (float*)d_out;

    float *p_h, *p_x1, *p_x2, *p_x3, *p_h4, *p_x4, *p_xsel, *p_y5, *p_y2, *p_y3,
          *p_emb, *p_hd, *p_w5t, *p_w6t;
    int* p_sel;
    cudaGetSymbolAddress((void**)&p_h,   g_h);
    cudaGetSymbolAddress((void**)&p_x1,  g_x1);
    cudaGetSymbolAddress((void**)&p_x2,  g_x2);
    cudaGetSymbolAddress((void**)&p_x3,  g_x3);
    cudaGetSymbolAddress((void**)&p_h4,  g_h4);
    cudaGetSymbolAddress((void**)&p_x4,  g_x4);
    cudaGetSymbolAddress((void**)&p_sel, g_sel);
    cudaGetSymbolAddress((void**)&p_xsel,g_xsel);
    cudaGetSymbolAddress((void**)&p_y5,  g_y5);
    cudaGetSymbolAddress((void**)&p_y2,  g_y2);
    cudaGetSymbolAddress((void**)&p_y3,  g_y3);
    cudaGetSymbolAddress((void**)&p_emb, g_emb);
    cudaGetSymbolAddress((void**)&p_hd,  g_hd);
    cudaGetSymbolAddress((void**)&p_w5t, g_w5t);
    cudaGetSymbolAddress((void**)&p_w6t, g_w6t);

    const size_t SMB = (size_t)(NPG*CCH*2 + NPG)*4 + (size_t)EPG*2*4;   // 102144
    cudaFuncSetAttribute(gcn_agg_k, cudaFuncAttributeMaxDynamicSharedMemorySize, (int)SMB);

    // degree / dis (deterministic, same every call)
    deg_init_k<<<(NN+255)/256, 256>>>();
    deg_cnt_k<<<(EE+255)/256, 256>>>(dst);
    deg_fin_k<<<(NN+255)/256, 256>>>();

    // weight reshapes
    tw5_k<<<(128*DD+255)/256, 256>>>(w5);
    tw6_k<<<(256*640+255)/256, 256>>>(w6);

    // GCN layer 1
    gemm_k<<<dim3(EMB/BN, NN/BM), 256>>>(x, W1, nullptr, p_h, NN, FEAT_IN, EMB, 0, 0);
    gcn_agg_k<<<GG*4, 256, SMB>>>(p_h, src, dst, b1, p_x1);
    // layer 2
    gemm_k<<<dim3(EMB/BN, NN/BM), 256>>>(p_x1, W2, nullptr, p_h, NN, EMB, EMB, 0, 0);
    gcn_agg_k<<<GG*4, 256, SMB>>>(p_h, src, dst, b2, p_x2);
    // layer 3
    gemm_k<<<dim3(EMB/BN, NN/BM), 256>>>(p_x2, W3, nullptr, p_h, NN, EMB, EMB, 0, 0);
    gcn_agg_k<<<GG*4, 256, SMB>>>(p_h, src, dst, b3, p_x3);
    // layer 4 (scalar channel)
    gemv4_k<<<(NN*32+255)/256, 256>>>(p_x3, W4, p_h4);
    gcn4_k<<<GG, 256>>>(p_h4, src, dst, b4, p_x4);

    // sort pooling + gather
    sortpool_k<<<GG, NPG>>>(p_x4, p_sel);
    gather_k<<<GG*KTOP, 256>>>(p_sel, p_xsel);

    // conv5 as GEMM [15840,769]x[769,128] + relu
    gemm_k<<<dim3(128/BN, (GG*KTOP + BM - 1)/BM), 256>>>(p_xsel, p_w5t, bc5, p_y5,
                                                          GG*KTOP, DD, 128, 1, 0);
    // maxpool (2,2)
    maxpool_k<<<(GG*15*128 + 255)/256, 256>>>(p_y5, p_y2);
    // conv6 as strided-row GEMM [5808,640]x[640,256] + relu
    gemm_k<<<dim3(EMB/BN, (GG*11 + BM - 1)/BM), 256>>>(p_y2, p_w6t, bc6, p_y3,
                                                        GG*11, 640, EMB, 1, 1);
    // reshape to emb [48, 30976]
    embre_k<<<GG*11, 256>>>(p_y3, p_emb);
    // dense layers
    dense1_k<<<dim3(BATCH, 4), 256>>>(p_emb, Wc1, bc1, p_hd);
    dense2_k<<<2, 256>>>(p_hd, Wc2, bc2, out);
}

// round 5
// speedup vs baseline: 1.2845x; 1.2845x over previous
#include <cuda_runtime.h>
#include <cuda_bf16.h>
#include <cstdint>
#include <math.h>

#define FEAT_IN 64
#define EMB     256
#define KTOP    30
#define BATCH   48
#define NGR     11
#define GG      528
#define NPG     192
#define EPG     384
#define NN      (GG*NPG)   // 101376
#define EE      (GG*EPG)   // 202752
#define DD      769
#define DENSE   2816
#define KIN     (NGR*DENSE)

// ================= scratch =================
__device__ float g_dis[NN];
__device__ float g_h[(long)NN*EMB];
__device__ float g_x1[(long)NN*EMB];
__device__ float g_x2[(long)NN*EMB];
__device__ float g_x3[(long)NN*EMB];
__device__ float g_h4[NN];
__device__ float g_x4[NN];
__device__ int   g_sel[GG*KTOP];
__device__ float g_xsel[(long)GG*KTOP*DD];
__device__ float g_y5[(long)GG*KTOP*128];
__device__ float g_y2[(long)GG*15*128];
__device__ float g_y3[(long)GG*11*EMB];
__device__ float g_emb[(long)BATCH*KIN];
__device__ float g_hd[BATCH*EMB];
__device__ float g_w5t[(long)DD*128];
__device__ float g_w6t[(long)640*EMB];

// ================= 3xTF32 mma.sync GEMM =================
// C[M,N] = A[M,K] @ B[K,N]  (A row-major fp32 (mode1: conv6 row remap),
// B row-major fp32). CTA tile 128x128, BK=32, 8 warps (2M x 4N), warp tile 64x32.
#define TBM 128
#define TBN 128
#define TBK 32
#define AS_STR 36     // uint2 stride for As rows (pad, conflict-free frags)
#define BS_STR 132    // uint2 stride for Bs rows
#define SM_GEMM ((TBM*AS_STR + TBK*BS_STR) * 8)   // 36864 + 33792 = 70656 B

__device__ __forceinline__ uint2 tf32_split(float v) {
    uint32_t hi;
    asm("cvt.rna.tf32.f32 %0, %1;" : "=r"(hi) : "f"(v));
    float r = v - __uint_as_float(hi);
    uint32_t lo;
    asm("cvt.rna.tf32.f32 %0, %1;" : "=r"(lo) : "f"(r));
    return make_uint2(hi, lo);
}
__device__ __forceinline__ void mma_tf32(float* d, uint32_t a0, uint32_t a1,
                                         uint32_t a2, uint32_t a3,
                                         uint32_t b0, uint32_t b1) {
    asm volatile("mma.sync.aligned.m16n8k8.row.col.f32.tf32.tf32.f32 "
        "{%0,%1,%2,%3}, {%4,%5,%6,%7}, {%8,%9}, {%0,%1,%2,%3};"
        : "+f"(d[0]), "+f"(d[1]), "+f"(d[2]), "+f"(d[3])
        : "r"(a0), "r"(a1), "r"(a2), "r"(a3), "r"(b0), "r"(b1));
}

__global__ __launch_bounds__(256, 1)
void gemm_tf32_k(const float* __restrict__ A, const float* __restrict__ B,
                 const float* __restrict__ bias, float* __restrict__ C,
                 int M, int K, int Nc, int relu, int mode)
{
    extern __shared__ char smem_raw[];
    uint2* As = (uint2*)smem_raw;                       // [TBM][AS_STR]
    uint2* Bs = (uint2*)(smem_raw + TBM*AS_STR*8);      // [TBK][BS_STR]

    int tid = threadIdx.x;
    int w   = tid >> 5, lane = tid & 31;
    int wm  = w & 1, wn = w >> 1;                       // 2 x 4 warp grid
    int grp = lane >> 2, qd = lane & 3;                 // t/4, t%4
    int row0 = blockIdx.y * TBM;
    int col0 = blockIdx.x * TBN;

    float acc[4][4][4];
    #pragma unroll
    for (int i = 0; i < 4; i++)
        #pragma unroll
        for (int j = 0; j < 4; j++)
            #pragma unroll
            for (int q = 0; q < 4; q++) acc[i][j][q] = 0.f;

    int chunks = (K + TBK - 1) / TBK;
    for (int c = 0; c < chunks; c++) {
        int k0 = c * TBK;
        // ---- load A tile: 128x32, convert to tf32 hi/lo ----
        #pragma unroll
        for (int q = 0; q < 16; q++) {
            int e = q*256 + tid;
            int m = e >> 5, kk = e & 31;
            int gm = row0 + m, gk = k0 + kk;
            float v = 0.f;
            if (gm < M && gk < K) {
                long base;
                if (mode == 0) base = (long)gm * K;
                else           base = (long)128 * (gm + 4*(gm/11));
                v = A[base + gk];
            }
            As[m*AS_STR + kk] = tf32_split(v);
        }
        // ---- load B tile: 32x128 ----
        #pragma unroll
        for (int q = 0; q < 16; q++) {
            int e = q*256 + tid;
            int kk = e >> 7, n = e & 127;
            int gk = k0 + kk;
            float v = (gk < K) ? B[(long)gk*Nc + col0 + n] : 0.f;
            Bs[kk*BS_STR + n] = tf32_split(v);
        }
        __syncthreads();
        // ---- compute: 4 k-steps of 8 ----
        #pragma unroll
        for (int ks = 0; ks < 4; ks++) {
            int kb = ks * 8;
            uint2 af[4][4];          // [mi][reg] (hi,lo)
            #pragma unroll
            for (int mi = 0; mi < 4; mi++) {
                int r = wm*64 + mi*16 + grp;
                af[mi][0] = As[(r   )*AS_STR + kb + qd    ];
                af[mi][1] = As[(r+8 )*AS_STR + kb + qd    ];
                af[mi][2] = As[(r   )*AS_STR + kb + qd + 4];
                af[mi][3] = As[(r+8 )*AS_STR + kb + qd + 4];
            }
            uint2 bf[4][2];          // [ni][reg]
            #pragma unroll
            for (int ni = 0; ni < 4; ni++) {
                int n = wn*32 + ni*8 + grp;
                bf[ni][0] = Bs[(kb + qd    )*BS_STR + n];
                bf[ni][1] = Bs[(kb + qd + 4)*BS_STR + n];
            }
            #pragma unroll
            for (int mi = 0; mi < 4; mi++)
                #pragma unroll
                for (int ni = 0; ni < 4; ni++) {
                    float* d = acc[mi][ni];
                    // lo x hi, hi x lo, hi x hi
                    mma_tf32(d, af[mi][0].y, af[mi][1].y, af[mi][2].y, af[mi][3].y,
                             bf[ni][0].x, bf[ni][1].x);
                    mma_tf32(d, af[mi][0].x, af[mi][1].x, af[mi][2].x, af[mi][3].x,
                             bf[ni][0].y, bf[ni][1].y);
                    mma_tf32(d, af[mi][0].x, af[mi][1].x, af[mi][2].x, af[mi][3].x,
                             bf[ni][0].x, bf[ni][1].x);
                }
        }
        __syncthreads();
    }
    // ---- epilogue ----
    #pragma unroll
    for (int mi = 0; mi < 4; mi++) {
        int r0 = row0 + wm*64 + mi*16 + grp;
        #pragma unroll
        for (int ni = 0; ni < 4; ni++) {
            int cc = col0 + wn*32 + ni*8 + 2*qd;
            float b0v = bias ? bias[cc] : 0.f;
            float b1v = bias ? bias[cc+1] : 0.f;
            float v0 = acc[mi][ni][0] + b0v, v1 = acc[mi][ni][1] + b1v;
            float v2 = acc[mi][ni][2] + b0v, v3 = acc[mi][ni][3] + b1v;
            if (relu) { v0 = fmaxf(v0,0.f); v1 = fmaxf(v1,0.f);
                        v2 = fmaxf(v2,0.f); v3 = fmaxf(v3,0.f); }
            if (r0 < M)     *(float2*)(C + (long)r0*Nc + cc)     = make_float2(v0, v1);
            if (r0+8 < M)   *(float2*)(C + (long)(r0+8)*Nc + cc) = make_float2(v2, v3);
        }
    }
}

// ================= degree =================
__global__ void deg_init_k() { int i = blockIdx.x*256+threadIdx.x; if (i < NN) g_dis[i] = 1.0f; }
__global__ void deg_cnt_k(const int* __restrict__ dst) {
    int e = blockIdx.x*256+threadIdx.x; if (e < EE) atomicAdd(&g_dis[dst[e]], 1.0f);
}
__global__ void deg_fin_k() { int i = blockIdx.x*256+threadIdx.x; if (i < NN) g_dis[i] = rsqrtf(g_dis[i]); }

// ================= conv weight reshapes =================
__global__ void tw5_k(const float* __restrict__ w5) {
    int i = blockIdx.x*256 + threadIdx.x;
    if (i < 128*DD) { int oc = i / DD, d = i % DD; g_w5t[(long)d*128 + oc] = w5[i]; }
}
__global__ void tw6_k(const float* __restrict__ w6) {
    int i = blockIdx.x*256 + threadIdx.x;
    if (i < 256*640) {
        int oc = i / 640, rem = i % 640;
        int ic = rem / 5, j = rem % 5;
        g_w6t[(long)(j*128 + ic)*256 + oc] = w6[i];
    }
}

// ================= GCN aggregation =================
#define CCH 64
__global__ void gcn_agg_k(const float* __restrict__ h, const int* __restrict__ src,
                          const int* __restrict__ dst, const float* __restrict__ bias,
                          float* __restrict__ out)
{
    extern __shared__ float sm[];
    float* hs   = sm;
    float* as   = hs + NPG*CCH;
    float* diss = as + NPG*CCH;
    int*  srcl  = (int*)(diss + NPG);
    int*  dstl  = srcl + EPG;
    int g = blockIdx.x >> 2;
    int chunk = blockIdx.x & 3;
    int tid = threadIdx.x;
    int c0 = chunk * CCH;

    for (int i = tid; i < NPG; i += 256) diss[i] = g_dis[g*NPG + i];
    for (int e = tid; e < EPG; e += 256) {
        srcl[e] = src[g*EPG + e] - g*NPG;
        dstl[e] = dst[g*EPG + e] - g*NPG;
    }
    __syncthreads();
    for (int f = tid; f < NPG*CCH; f += 256) {
        int node = f >> 6, c = f & 63;
        float v = h[(long)(g*NPG + node)*EMB + c0 + c];
        hs[f] = v;
        float d = diss[node];
        as[f] = v * d * d;
    }
    __syncthreads();
    int esub = tid >> 6, c = tid & 63;
    for (int e0 = 0; e0 < EPG; e0 += 4) {
        int e = e0 + esub;
        int s = srcl[e], d = dstl[e];
        float coef = diss[s] * diss[d];
        atomicAdd(&as[d*CCH + c], hs[s*CCH + c] * coef);
    }
    __syncthreads();
    for (int f = tid; f < NPG*CCH; f += 256) {
        int node = f >> 6, cc = f & 63;
        out[(long)(g*NPG + node)*EMB + c0 + cc] = tanhf(as[f] + bias[c0 + cc]);
    }
}

// ================= layer 4 =================
__global__ void gemv4_k(const float* __restrict__ x3, const float* __restrict__ W4,
                        float* __restrict__ h4)
{
    int warp = (blockIdx.x*blockDim.x + threadIdx.x) >> 5;
    int lane = threadIdx.x & 31;
    if (warp >= NN) return;
    const float* row = x3 + (long)warp*EMB;
    float s = 0.f;
    #pragma unroll 4
    for (int c = lane; c < EMB; c += 32) s += row[c] * W4[c];
    #pragma unroll
    for (int o = 16; o > 0; o >>= 1) s += __shfl_down_sync(0xffffffffu, s, o);
    if (lane == 0) h4[warp] = s;
}
__global__ void gcn4_k(const float* __restrict__ h4, const int* __restrict__ src,
                       const int* __restrict__ dst, const float* __restrict__ b4,
                       float* __restrict__ x4out)
{
    __shared__ float hv[NPG], av[NPG], dv[NPG];
    int g = blockIdx.x, tid = threadIdx.x;
    for (int i = tid; i < NPG; i += 256) {
        float v = h4[g*NPG + i];
        float d = g_dis[g*NPG + i];
        hv[i] = v; dv[i] = d; av[i] = v*d*d;
    }
    __syncthreads();
    for (int e = tid; e < EPG; e += 256) {
        int s = src[g*EPG + e] - g*NPG;
        int d = dst[g*EPG + e] - g*NPG;
        atomicAdd(&av[d], hv[s]*dv[s]*dv[d]);
    }
    __syncthreads();
    float bb = b4[0];
    for (int i = tid; i < NPG; i += 256)
        x4out[g*NPG + i] = tanhf(av[i] + bb);
}

// ================= sort pool / gather =================
__global__ void sortpool_k(const float* __restrict__ x4, int* __restrict__ sel)
{
    __shared__ float v[NPG];
    int g = blockIdx.x, t = threadIdx.x;
    v[t] = x4[g*NPG + t];
    __syncthreads();
    float mv = v[t];
    int rank = 0;
    for (int j = 0; j < NPG; j++) {
        float o = v[j];
        rank += (o > mv) || (o == mv && j < t);
    }
    if (rank < KTOP) sel[g*KTOP + rank] = t;
}
__global__ void gather_k(const int* __restrict__ sel, float* __restrict__ xsel)
{
    int r = blockIdx.x;
    int g = r / KTOP;
    long node = (long)g*NPG + sel[r];
    float* o = xsel + (long)r*DD;
    int t = threadIdx.x;
    o[t]        = g_x1[node*EMB + t];
    o[256 + t]  = g_x2[node*EMB + t];
    o[512 + t]  = g_x3[node*EMB + t];
    if (t == 0) o[768] = g_x4[node];
}

// ================= maxpool / reshape / dense =================
__global__ void maxpool_k(const float* __restrict__ y5, float* __restrict__ y2)
{
    int idx = blockIdx.x*blockDim.x + threadIdx.x;
    if (idx >= GG*15*128) return;
    int oc = idx & 127;
    int p  = (idx >> 7) % 15;
    int g  = idx / (15*128);
    float a = y5[((long)g*KTOP + 2*p)*128 + oc];
    float b = y5[((long)g*KTOP + 2*p + 1)*128 + oc];
    y2[idx] = fmaxf(a, b);
}
__global__ void embre_k(const float* __restrict__ y3, float* __restrict__ emb)
{
    int r = blockIdx.x;
    int oc = threadIdx.x;
    int g = r / 11, t = r % 11;
    int b = g / NGR, ng = g % NGR;
    emb[(long)b*KIN + ng*DENSE + oc*11 + t] = y3[(long)r*EMB + oc];
}
__global__ void dense1_k(const float* __restrict__ emb, const float* __restrict__ Wc1,
                         const float* __restrict__ bc1, float* __restrict__ hd)
{
    int b = blockIdx.x, ch = blockIdx.y;
    int tid = threadIdx.x;
    int oc = ch*64 + (tid & 63);
    int s = tid >> 6;
    const int SL = KIN / 4;
    const float* arow = emb + (long)b*KIN;
    float acc = 0.f;
    int i0 = s*SL, i1 = i0 + SL;
    #pragma unroll 4
    for (int i = i0; i < i1; i++) acc += arow[i] * Wc1[(long)i*EMB + oc];
    __shared__ float red[256];
    red[tid] = acc;
    __syncthreads();
    if (s == 0) {
        float v = red[tid] + red[tid+64] + red[tid+128] + red[tid+192] + bc1[oc];
        hd[b*EMB + oc] = fmaxf(v, 0.f);
    }
}
__global__ void dense2_k(const float* __restrict__ hd, const float* __restrict__ Wc2,
                         const float* __restrict__ bc2, float* __restrict__ out)
{
    int t = blockIdx.x*blockDim.x + threadIdx.x;
    if (t >= BATCH*10) return;
    int b = t / 10, o = t % 10;
    float s = bc2[o];
    #pragma unroll 8
    for (int k = 0; k < EMB; k++) s += hd[b*EMB + k] * Wc2[k*10 + o];
    out[t] = s;
}

// ================= launch =================
extern "C" void kernel_launch(void* const* d_in, const int* in_sizes, int n_in,
                              void* d_out, int out_size)
{
    const float* x   = (const float*)d_in[0];
    const int*   src = (const int*)d_in[1];
    const int*   dst = (const int*)d_in[2];
    const float* W1  = (const float*)d_in[3];
    const float* b1  = (const float*)d_in[4];
    const float* W2  = (const float*)d_in[5];
    const float* b2  = (const float*)d_in[6];
    const float* W3  = (const float*)d_in[7];
    const float* b3  = (const float*)d_in[8];
    const float* W4  = (const float*)d_in[9];
    const float* b4  = (const float*)d_in[10];
    const float* w5  = (const float*)d_in[11];
    const float* bc5 = (const float*)d_in[12];
    const float* w6  = (const float*)d_in[13];
    const float* bc6 = (const float*)d_in[14];
    const float* Wc1 = (const float*)d_in[15];
    const float* bc1 = (const float*)d_in[16];
    const float* Wc2 = (const float*)d_in[17];
    const float* bc2 = (const float*)d_in[18];
    float* out = (float*)d_out;

    float *p_h, *p_x1, *p_x2, *p_x3, *p_h4, *p_x4, *p_xsel, *p_y5, *p_y2, *p_y3,
          *p_emb, *p_hd, *p_w5t, *p_w6t;
    int* p_sel;
    cudaGetSymbolAddress((void**)&p_h,   g_h);
    cudaGetSymbolAddress((void**)&p_x1,  g_x1);
    cudaGetSymbolAddress((void**)&p_x2,  g_x2);
    cudaGetSymbolAddress((void**)&p_x3,  g_x3);
    cudaGetSymbolAddress((void**)&p_h4,  g_h4);
    cudaGetSymbolAddress((void**)&p_x4,  g_x4);
    cudaGetSymbolAddress((void**)&p_sel, g_sel);
    cudaGetSymbolAddress((void**)&p_xsel,g_xsel);
    cudaGetSymbolAddress((void**)&p_y5,  g_y5);
    cudaGetSymbolAddress((void**)&p_y2,  g_y2);
    cudaGetSymbolAddress((void**)&p_y3,  g_y3);
    cudaGetSymbolAddress((void**)&p_emb, g_emb);
    cudaGetSymbolAddress((void**)&p_hd,  g_hd);
    cudaGetSymbolAddress((void**)&p_w5t, g_w5t);
    cudaGetSymbolAddress((void**)&p_w6t, g_w6t);

    const size_t SMB = (size_t)(NPG*CCH*2 + NPG)*4 + (size_t)EPG*2*4;
    cudaFuncSetAttribute(gcn_agg_k, cudaFuncAttributeMaxDynamicSharedMemorySize, (int)SMB);
    cudaFuncSetAttribute(gemm_tf32_k, cudaFuncAttributeMaxDynamicSharedMemorySize, SM_GEMM);

    // degree
    deg_init_k<<<(NN+255)/256, 256>>>();
    deg_cnt_k<<<(EE+255)/256, 256>>>(dst);
    deg_fin_k<<<(NN+255)/256, 256>>>();

    // conv weight reshapes
    tw5_k<<<(128*DD+255)/256, 256>>>(w5);
    tw6_k<<<(256*640+255)/256, 256>>>(w6);

    // GCN layers 1-3 (3xTF32 tensor GEMM + smem aggregation)
    gemm_tf32_k<<<dim3(EMB/TBN, NN/TBM), 256, SM_GEMM>>>(x, W1, nullptr, p_h, NN, FEAT_IN, EMB, 0, 0);
    gcn_agg_k<<<GG*4, 256, SMB>>>(p_h, src, dst, b1, p_x1);
    gemm_tf32_k<<<dim3(EMB/TBN, NN/TBM), 256, SM_GEMM>>>(p_x1, W2, nullptr, p_h, NN, EMB, EMB, 0, 0);
    gcn_agg_k<<<GG*4, 256, SMB>>>(p_h, src, dst, b2, p_x2);
    gemm_tf32_k<<<dim3(EMB/TBN, NN/TBM), 256, SM_GEMM>>>(p_x2, W3, nullptr, p_h, NN, EMB, EMB, 0, 0);
    gcn_agg_k<<<GG*4, 256, SMB>>>(p_h, src, dst, b3, p_x3);
    // layer 4
    gemv4_k<<<(NN*32+255)/256, 256>>>(p_x3, W4, p_h4);
    gcn4_k<<<GG, 256>>>(p_h4, src, dst, b4, p_x4);

    // sort pooling + gather
    sortpool_k<<<GG, NPG>>>(p_x4, p_sel);
    gather_k<<<GG*KTOP, 256>>>(p_sel, p_xsel);

    // conv5 as GEMM [15840,769]x[769,128] + relu
    gemm_tf32_k<<<dim3(1, (GG*KTOP + TBM - 1)/TBM), 256, SM_GEMM>>>(p_xsel, p_w5t, bc5, p_y5,
                                                                     GG*KTOP, DD, 128, 1, 0);
    maxpool_k<<<(GG*15*128 + 255)/256, 256>>>(p_y5, p_y2);
    // conv6 as strided-row GEMM [5808,640]x[640,256] + relu
    gemm_tf32_k<<<dim3(EMB/TBN, (GG*11 + TBM - 1)/TBM), 256, SM_GEMM>>>(p_y2, p_w6t, bc6, p_y3,
                                                                         GG*11, 640, EMB, 1, 1);
    embre_k<<<GG*11, 256>>>(p_y3, p_emb);
    dense1_k<<<dim3(BATCH, 4), 256>>>(p_emb, Wc1, bc1, p_hd);
    dense2_k<<<2, 256>>>(p_hd, Wc2, bc2, out);
}

// round 6
// speedup vs baseline: 1.3240x; 1.0307x over previous
#include <cuda_runtime.h>
#include <cuda_bf16.h>
#include <cstdint>
#include <math.h>

#define FEAT_IN 64
#define EMB     256
#define KTOP    30
#define BATCH   48
#define NGR     11
#define GG      528
#define NPG     192
#define EPG     384
#define NN      (GG*NPG)   // 101376
#define EE      (GG*EPG)   // 202752
#define DD      769
#define KP5     800        // conv5 K padded to 32
#define DENSE   2816
#define KIN     (NGR*DENSE)

// ================= scratch =================
__device__ float g_dis[NN];
__device__ float g_h[(long)NN*EMB];
__device__ float g_x1[(long)NN*EMB];
__device__ float g_x2[(long)NN*EMB];
__device__ float g_x3[(long)NN*EMB];
__device__ float g_h4[NN];
__device__ float g_x4[NN];
__device__ int   g_sel[GG*KTOP];
__device__ float g_y5[(long)GG*KTOP*128];
__device__ float g_y3[(long)GG*11*EMB];
__device__ float g_emb[(long)BATCH*KIN];
__device__ float g_hd[BATCH*EMB];
// pre-split tf32 (hi,lo) planes
__device__ uint2 g_sx[(long)NN*FEAT_IN];        // x split (layer1 A)
__device__ uint2 g_s[(long)NN*EMB];             // x1/x2 split (layer2/3 A)
__device__ uint2 g_wb[3][EMB*EMB];              // W1..W3 planes [K][256]
__device__ uint2 g_w5p[(long)KP5*128];          // conv5 B plane [800][128]
__device__ uint2 g_w6p[(long)640*EMB];          // conv6 B plane [640][256]
__device__ uint2 g_xselp[(long)GG*KTOP*KP5];    // conv5 A plane [15840][800]
__device__ uint2 g_y2p[(long)GG*15*128];        // conv6 A plane (remapped rows)

// ================= helpers =================
__device__ __forceinline__ uint32_t smem_u32(const void* p) {
    uint32_t a;
    asm("{ .reg .u64 t; cvta.to.shared.u64 t, %1; cvt.u32.u64 %0, t; }" : "=r"(a) : "l"(p));
    return a;
}
__device__ __forceinline__ uint2 tf32_split(float v) {
    uint32_t hi;
    asm("cvt.rna.tf32.f32 %0, %1;" : "=r"(hi) : "f"(v));
    float r = v - __uint_as_float(hi);
    uint32_t lo;
    asm("cvt.rna.tf32.f32 %0, %1;" : "=r"(lo) : "f"(r));
    return make_uint2(hi, lo);
}
__device__ __forceinline__ void mma_tf32(float* d, uint32_t a0, uint32_t a1,
                                         uint32_t a2, uint32_t a3,
                                         uint32_t b0, uint32_t b1) {
    asm volatile("mma.sync.aligned.m16n8k8.row.col.f32.tf32.tf32.f32 "
        "{%0,%1,%2,%3}, {%4,%5,%6,%7}, {%8,%9}, {%0,%1,%2,%3};"
        : "+f"(d[0]), "+f"(d[1]), "+f"(d[2]), "+f"(d[3])
        : "r"(a0), "r"(a1), "r"(a2), "r"(a3), "r"(b0), "r"(b1));
}
__device__ __forceinline__ void cp16(uint32_t dst, const void* src, bool valid) {
    int sz = valid ? 16 : 0;
    asm volatile("cp.async.cg.shared.global [%0], [%1], 16, %2;"
                 :: "r"(dst), "l"(src), "r"(sz));
}
#define CP_COMMIT() asm volatile("cp.async.commit_group;" ::: "memory")
#define CP_WAIT0()  asm volatile("cp.async.wait_group 0;" ::: "memory")
#define CP_WAIT1()  asm volatile("cp.async.wait_group 1;" ::: "memory")

// ================= double-buffered TF32 GEMM =================
// C[M,Nc] = A[M,K] @ B[K,Nc], operands pre-split tf32 (hi,lo) uint2 planes.
// CTA tile 128x128, BK=32, 8 warps (2Mx4N), warp tile 64x32, 3 mma products.
#define TBM 128
#define TBN 128
#define TBK 32
#define AS_STR 36       // uint2 stride (288 B rows)
#define BS_STR 132      // uint2 stride (1056 B rows)
#define ST_A_B (TBM*AS_STR*8)            // 36864
#define ST_B_B (TBK*BS_STR*8)            // 33792
#define STAGE_B (ST_A_B + ST_B_B)        // 70656
#define SM_GEMM2 (2*STAGE_B + 512)       // + rowbase

__global__ __launch_bounds__(256, 1)
void gemm2_k(const uint2* __restrict__ A, const uint2* __restrict__ B,
             const float* __restrict__ bias, float* __restrict__ C,
             int M, int K, int Nc, int relu, int mode, int ldA)
{
    extern __shared__ char smem_raw[];
    int* rowbase = (int*)(smem_raw + 2*STAGE_B);
    uint32_t sbase = smem_u32(smem_raw);

    int tid = threadIdx.x;
    int w   = tid >> 5, lane = tid & 31;
    int wm  = w & 1, wn = w >> 1;
    int grp = lane >> 2, qd = lane & 3;
    int row0 = blockIdx.y * TBM;
    int col0 = blockIdx.x * TBN;

    if (tid < TBM) {
        int gm = row0 + tid;
        int base = -1;
        if (gm < M) base = (mode == 0) ? gm * ldA : 128 * (gm + 4*(gm/11));
        rowbase[tid] = base;
    }
    __syncthreads();

    float acc[4][4][4];
    #pragma unroll
    for (int i = 0; i < 4; i++)
        #pragma unroll
        for (int j = 0; j < 4; j++)
            #pragma unroll
            for (int q = 0; q < 4; q++) acc[i][j][q] = 0.f;

    int chunks = K / TBK;

    // issue chunk helper (inlined via lambda-free macro-ish code)
    #define ISSUE(cidx, stg) do {                                               \
        int _k0 = (cidx) * TBK;                                                 \
        uint32_t _st = sbase + (stg) * STAGE_B;                                 \
        _Pragma("unroll")                                                       \
        for (int q = 0; q < 8; q++) {                                           \
            int f = q*256 + tid;                                                \
            int m = f >> 4, u = f & 15;                                         \
            int rb = rowbase[m];                                                \
            uint32_t dst = _st + m*288 + u*16;                                  \
            const void* srcp = (rb >= 0) ? (const void*)(A + (long)rb + _k0 + u*2) \
                                         : (const void*)A;                      \
            cp16(dst, srcp, rb >= 0);                                           \
        }                                                                       \
        _Pragma("unroll")                                                       \
        for (int q = 0; q < 8; q++) {                                           \
            int f = q*256 + tid;                                                \
            int kk = f >> 6, u = f & 63;                                        \
            uint32_t dst = _st + ST_A_B + kk*1056 + u*16;                       \
            cp16(dst, (const void*)(B + (long)(_k0 + kk)*Nc + col0 + u*2), true);\
        }                                                                       \
    } while (0)

    ISSUE(0, 0);
    CP_COMMIT();

    for (int c = 0; c < chunks; c++) {
        if (c + 1 < chunks) {
            ISSUE(c + 1, (c + 1) & 1);
            CP_COMMIT();
            CP_WAIT1();
        } else {
            CP_WAIT0();
        }
        __syncthreads();

        const uint2* As = (const uint2*)(smem_raw + (c & 1) * STAGE_B);
        const uint2* Bs = (const uint2*)(smem_raw + (c & 1) * STAGE_B + ST_A_B);

        #pragma unroll
        for (int ks = 0; ks < 4; ks++) {
            int kb = ks * 8;
            uint2 af[4][4];
            #pragma unroll
            for (int mi = 0; mi < 4; mi++) {
                int r = wm*64 + mi*16 + grp;
                af[mi][0] = As[(r   )*AS_STR + kb + qd    ];
                af[mi][1] = As[(r+8 )*AS_STR + kb + qd    ];
                af[mi][2] = As[(r   )*AS_STR + kb + qd + 4];
                af[mi][3] = As[(r+8 )*AS_STR + kb + qd + 4];
            }
            uint2 bf[4][2];
            #pragma unroll
            for (int ni = 0; ni < 4; ni++) {
                int n = wn*32 + ni*8 + grp;
                bf[ni][0] = Bs[(kb + qd    )*BS_STR + n];
                bf[ni][1] = Bs[(kb + qd + 4)*BS_STR + n];
            }
            #pragma unroll
            for (int mi = 0; mi < 4; mi++)
                #pragma unroll
                for (int ni = 0; ni < 4; ni++) {
                    float* d = acc[mi][ni];
                    mma_tf32(d, af[mi][0].y, af[mi][1].y, af[mi][2].y, af[mi][3].y,
                             bf[ni][0].x, bf[ni][1].x);
                    mma_tf32(d, af[mi][0].x, af[mi][1].x, af[mi][2].x, af[mi][3].x,
                             bf[ni][0].y, bf[ni][1].y);
                    mma_tf32(d, af[mi][0].x, af[mi][1].x, af[mi][2].x, af[mi][3].x,
                             bf[ni][0].x, bf[ni][1].x);
                }
        }
        __syncthreads();
    }
    #undef ISSUE

    // ---- epilogue ----
    #pragma unroll
    for (int mi = 0; mi < 4; mi++) {
        int r0 = row0 + wm*64 + mi*16 + grp;
        #pragma unroll
        for (int ni = 0; ni < 4; ni++) {
            int cc = col0 + wn*32 + ni*8 + 2*qd;
            float b0v = bias ? bias[cc] : 0.f;
            float b1v = bias ? bias[cc+1] : 0.f;
            float v0 = acc[mi][ni][0] + b0v, v1 = acc[mi][ni][1] + b1v;
            float v2 = acc[mi][ni][2] + b0v, v3 = acc[mi][ni][3] + b1v;
            if (relu) { v0 = fmaxf(v0,0.f); v1 = fmaxf(v1,0.f);
                        v2 = fmaxf(v2,0.f); v3 = fmaxf(v3,0.f); }
            if (r0 < M)     *(float2*)(C + (long)r0*Nc + cc)     = make_float2(v0, v1);
            if (r0+8 < M)   *(float2*)(C + (long)(r0+8)*Nc + cc) = make_float2(v2, v3);
        }
    }
}

// ================= degree =================
__global__ void deg_init_k() { int i = blockIdx.x*256+threadIdx.x; if (i < NN) g_dis[i] = 1.0f; }
__global__ void deg_cnt_k(const int* __restrict__ dst) {
    int e = blockIdx.x*256+threadIdx.x; if (e < EE) atomicAdd(&g_dis[dst[e]], 1.0f);
}
__global__ void deg_fin_k() { int i = blockIdx.x*256+threadIdx.x; if (i < NN) g_dis[i] = rsqrtf(g_dis[i]); }

// ================= input / weight split kernels =================
__global__ void splitx_k(const float* __restrict__ x) {
    long i = (long)blockIdx.x*256 + threadIdx.x;
    if (i < (long)NN*FEAT_IN) g_sx[i] = tf32_split(x[i]);
}
__global__ void wsplit_k(const float* __restrict__ W, uint2* __restrict__ o, int n) {
    int i = blockIdx.x*256 + threadIdx.x;
    if (i < n) o[i] = tf32_split(W[i]);
}
__global__ void tw5_k(const float* __restrict__ w5) {
    int i = blockIdx.x*256 + threadIdx.x;          // over 800*128
    if (i >= KP5*128) return;
    int d = i >> 7, oc = i & 127;
    float v = (d < DD) ? w5[oc*DD + d] : 0.f;
    g_w5p[i] = tf32_split(v);
}
__global__ void tw6_k(const float* __restrict__ w6) {
    int i = blockIdx.x*256 + threadIdx.x;          // over 640*256
    if (i >= 640*EMB) return;
    int kr = i >> 8, oc = i & 255;
    int j = kr >> 7, ic = kr & 127;
    g_w6p[i] = tf32_split(w6[oc*640 + ic*5 + j]);
}

// ================= GCN aggregation (+fused split) =================
#define CCH 64
__global__ void gcn_agg_k(const float* __restrict__ h, const int* __restrict__ src,
                          const int* __restrict__ dst, const float* __restrict__ bias,
                          float* __restrict__ out, uint2* __restrict__ sp)
{
    extern __shared__ float sm[];
    float* hs   = sm;
    float* as   = hs + NPG*CCH;
    float* diss = as + NPG*CCH;
    int*  srcl  = (int*)(diss + NPG);
    int*  dstl  = srcl + EPG;
    int g = blockIdx.x >> 2;
    int chunk = blockIdx.x & 3;
    int tid = threadIdx.x;
    int c0 = chunk * CCH;

    for (int i = tid; i < NPG; i += 256) diss[i] = g_dis[g*NPG + i];
    for (int e = tid; e < EPG; e += 256) {
        srcl[e] = src[g*EPG + e] - g*NPG;
        dstl[e] = dst[g*EPG + e] - g*NPG;
    }
    __syncthreads();
    for (int f = tid; f < NPG*CCH; f += 256) {
        int node = f >> 6, c = f & 63;
        float v = h[(long)(g*NPG + node)*EMB + c0 + c];
        hs[f] = v;
        float d = diss[node];
        as[f] = v * d * d;
    }
    __syncthreads();
    int esub = tid >> 6, c = tid & 63;
    for (int e0 = 0; e0 < EPG; e0 += 4) {
        int e = e0 + esub;
        int s = srcl[e], d = dstl[e];
        float coef = diss[s] * diss[d];
        atomicAdd(&as[d*CCH + c], hs[s*CCH + c] * coef);
    }
    __syncthreads();
    for (int f = tid; f < NPG*CCH; f += 256) {
        int node = f >> 6, cc = f & 63;
        long o = (long)(g*NPG + node)*EMB + c0 + cc;
        float v = tanhf(as[f] + bias[c0 + cc]);
        out[o] = v;
        if (sp) sp[o] = tf32_split(v);
    }
}

// ================= layer 4 =================
__global__ void gemv4_k(const float* __restrict__ x3, const float* __restrict__ W4,
                        float* __restrict__ h4)
{
    int warp = (blockIdx.x*blockDim.x + threadIdx.x) >> 5;
    int lane = threadIdx.x & 31;
    if (warp >= NN) return;
    const float* row = x3 + (long)warp*EMB;
    float s = 0.f;
    #pragma unroll 4
    for (int c = lane; c < EMB; c += 32) s += row[c] * W4[c];
    #pragma unroll
    for (int o = 16; o > 0; o >>= 1) s += __shfl_down_sync(0xffffffffu, s, o);
    if (lane == 0) h4[warp] = s;
}
__global__ void gcn4_k(const float* __restrict__ h4, const int* __restrict__ src,
                       const int* __restrict__ dst, const float* __restrict__ b4,
                       float* __restrict__ x4out)
{
    __shared__ float hv[NPG], av[NPG], dv[NPG];
    int g = blockIdx.x, tid = threadIdx.x;
    for (int i = tid; i < NPG; i += 256) {
        float v = h4[g*NPG + i];
        float d = g_dis[g*NPG + i];
        hv[i] = v; dv[i] = d; av[i] = v*d*d;
    }
    __syncthreads();
    for (int e = tid; e < EPG; e += 256) {
        int s = src[g*EPG + e] - g*NPG;
        int d = dst[g*EPG + e] - g*NPG;
        atomicAdd(&av[d], hv[s]*dv[s]*dv[d]);
    }
    __syncthreads();
    float bb = b4[0];
    for (int i = tid; i < NPG; i += 256)
        x4out[g*NPG + i] = tanhf(av[i] + bb);
}

// ================= sort pool / gather (fused split to conv5 A plane) =================
__global__ void sortpool_k(const float* __restrict__ x4, int* __restrict__ sel)
{
    __shared__ float v[NPG];
    int g = blockIdx.x, t = threadIdx.x;
    v[t] = x4[g*NPG + t];
    __syncthreads();
    float mv = v[t];
    int rank = 0;
    for (int j = 0; j < NPG; j++) {
        float o = v[j];
        rank += (o > mv) || (o == mv && j < t);
    }
    if (rank < KTOP) sel[g*KTOP + rank] = t;
}
__global__ void gather_k(const int* __restrict__ sel)
{
    int r = blockIdx.x;                 // 0..G*K-1
    int g = r / KTOP;
    long node = (long)g*NPG + sel[r];
    uint2* o = g_xselp + (long)r*KP5;
    int t = threadIdx.x;                // 256
    o[t]        = tf32_split(g_x1[node*EMB + t]);
    o[256 + t]  = tf32_split(g_x2[node*EMB + t]);
    o[512 + t]  = tf32_split(g_x3[node*EMB + t]);
    if (t == 0) o[768] = tf32_split(g_x4[node]);
    if (t < KP5 - DD) o[DD + t] = make_uint2(0u, 0u);
}

// ================= maxpool (fused split to conv6 A plane) =================
__global__ void maxpool_k(const float* __restrict__ y5)
{
    int idx = blockIdx.x*blockDim.x + threadIdx.x;
    if (idx >= GG*15*128) return;
    int oc = idx & 127;
    int p  = (idx >> 7) % 15;
    int g  = idx / (15*128);
    float a = y5[((long)g*KTOP + 2*p)*128 + oc];
    float b = y5[((long)g*KTOP + 2*p + 1)*128 + oc];
    g_y2p[idx] = tf32_split(fmaxf(a, b));
}

// ================= reshape / dense =================
__global__ void embre_k(const float* __restrict__ y3, float* __restrict__ emb)
{
    int r = blockIdx.x;
    int oc = threadIdx.x;
    int g = r / 11, t = r % 11;
    int b = g / NGR, ng = g % NGR;
    emb[(long)b*KIN + ng*DENSE + oc*11 + t] = y3[(long)r*EMB + oc];
}
__global__ void dense1_k(const float* __restrict__ emb, const float* __restrict__ Wc1,
                         const float* __restrict__ bc1, float* __restrict__ hd)
{
    int b = blockIdx.x, ch = blockIdx.y;
    int tid = threadIdx.x;
    int oc = ch*64 + (tid & 63);
    int s = tid >> 6;
    const int SL = KIN / 4;
    const float* arow = emb + (long)b*KIN;
    float acc = 0.f;
    int i0 = s*SL, i1 = i0 + SL;
    #pragma unroll 4
    for (int i = i0; i < i1; i++) acc += arow[i] * Wc1[(long)i*EMB + oc];
    __shared__ float red[256];
    red[tid] = acc;
    __syncthreads();
    if (s == 0) {
        float v = red[tid] + red[tid+64] + red[tid+128] + red[tid+192] + bc1[oc];
        hd[b*EMB + oc] = fmaxf(v, 0.f);
    }
}
__global__ void dense2_k(const float* __restrict__ hd, const float* __restrict__ Wc2,
                         const float* __restrict__ bc2, float* __restrict__ out)
{
    int t = blockIdx.x*blockDim.x + threadIdx.x;
    if (t >= BATCH*10) return;
    int b = t / 10, o = t % 10;
    float s = bc2[o];
    #pragma unroll 8
    for (int k = 0; k < EMB; k++) s += hd[b*EMB + k] * Wc2[k*10 + o];
    out[t] = s;
}

// ================= launch =================
extern "C" void kernel_launch(void* const* d_in, const int* in_sizes, int n_in,
                              void* d_out, int out_size)
{
    const float* x   = (const float*)d_in[0];
    const int*   src = (const int*)d_in[1];
    const int*   dst = (const int*)d_in[2];
    const float* W1  = (const float*)d_in[3];
    const float* b1  = (const float*)d_in[4];
    const float* W2  = (const float*)d_in[5];
    const float* b2  = (const float*)d_in[6];
    const float* W3  = (const float*)d_in[7];
    const float* b3  = (const float*)d_in[8];
    const float* W4  = (const float*)d_in[9];
    const float* b4  = (const float*)d_in[10];
    const float* w5  = (const float*)d_in[11];
    const float* bc5 = (const float*)d_in[12];
    const float* w6  = (const float*)d_in[13];
    const float* bc6 = (const float*)d_in[14];
    const float* Wc1 = (const float*)d_in[15];
    const float* bc1 = (const float*)d_in[16];
    const float* Wc2 = (const float*)d_in[17];
    const float* bc2 = (const float*)d_in[18];
    float* out = (float*)d_out;

    float *p_h, *p_x1, *p_x2, *p_x3, *p_h4, *p_x4, *p_y5, *p_y3, *p_emb, *p_hd;
    int* p_sel;
    uint2 *p_sx, *p_s, *p_wb, *p_w5p, *p_w6p, *p_xselp, *p_y2p;
    cudaGetSymbolAddress((void**)&p_h,    g_h);
    cudaGetSymbolAddress((void**)&p_x1,   g_x1);
    cudaGetSymbolAddress((void**)&p_x2,   g_x2);
    cudaGetSymbolAddress((void**)&p_x3,   g_x3);
    cudaGetSymbolAddress((void**)&p_h4,   g_h4);
    cudaGetSymbolAddress((void**)&p_x4,   g_x4);
    cudaGetSymbolAddress((void**)&p_sel,  g_sel);
    cudaGetSymbolAddress((void**)&p_y5,   g_y5);
    cudaGetSymbolAddress((void**)&p_y3,   g_y3);
    cudaGetSymbolAddress((void**)&p_emb,  g_emb);
    cudaGetSymbolAddress((void**)&p_hd,   g_hd);
    cudaGetSymbolAddress((void**)&p_sx,   g_sx);
    cudaGetSymbolAddress((void**)&p_s,    g_s);
    cudaGetSymbolAddress((void**)&p_wb,   g_wb);
    cudaGetSymbolAddress((void**)&p_w5p,  g_w5p);
    cudaGetSymbolAddress((void**)&p_w6p,  g_w6p);
    cudaGetSymbolAddress((void**)&p_xselp,g_xselp);
    cudaGetSymbolAddress((void**)&p_y2p,  g_y2p);

    const size_t SMB = (size_t)(NPG*CCH*2 + NPG)*4 + (size_t)EPG*2*4;
    cudaFuncSetAttribute(gcn_agg_k, cudaFuncAttributeMaxDynamicSharedMemorySize, (int)SMB);
    cudaFuncSetAttribute(gemm2_k, cudaFuncAttributeMaxDynamicSharedMemorySize, SM_GEMM2);

    // degree
    deg_init_k<<<(NN+255)/256, 256>>>();
    deg_cnt_k<<<(EE+255)/256, 256>>>(dst);
    deg_fin_k<<<(NN+255)/256, 256>>>();

    // weight / input splits
    wsplit_k<<<(FEAT_IN*256+255)/256, 256>>>(W1, p_wb + 0L*EMB*EMB, FEAT_IN*256);
    wsplit_k<<<(EMB*256+255)/256, 256>>>(W2, p_wb + 1L*EMB*EMB, EMB*256);
    wsplit_k<<<(EMB*256+255)/256, 256>>>(W3, p_wb + 2L*EMB*EMB, EMB*256);
    tw5_k<<<(KP5*128+255)/256, 256>>>(w5);
    tw6_k<<<(640*EMB+255)/256, 256>>>(w6);
    splitx_k<<<(int)(((long)NN*FEAT_IN+255)/256), 256>>>(x);

    // GCN layers 1-3
    gemm2_k<<<dim3(EMB/TBN, NN/TBM), 256, SM_GEMM2>>>(p_sx, p_wb + 0L*EMB*EMB, nullptr, p_h,
                                                       NN, FEAT_IN, EMB, 0, 0, FEAT_IN);
    gcn_agg_k<<<GG*4, 256, SMB>>>(p_h, src, dst, b1, p_x1, p_s);
    gemm2_k<<<dim3(EMB/TBN, NN/TBM), 256, SM_GEMM2>>>(p_s, p_wb + 1L*EMB*EMB, nullptr, p_h,
                                                       NN, EMB, EMB, 0, 0, EMB);
    gcn_agg_k<<<GG*4, 256, SMB>>>(p_h, src, dst, b2, p_x2, p_s);
    gemm2_k<<<dim3(EMB/TBN, NN/TBM), 256, SM_GEMM2>>>(p_s, p_wb + 2L*EMB*EMB, nullptr, p_h,
                                                       NN, EMB, EMB, 0, 0, EMB);
    gcn_agg_k<<<GG*4, 256, SMB>>>(p_h, src, dst, b3, p_x3, nullptr);
    // layer 4
    gemv4_k<<<(NN*32+255)/256, 256>>>(p_x3, W4, p_h4);
    gcn4_k<<<GG, 256>>>(p_h4, src, dst, b4, p_x4);

    // sort pooling + gather (writes split conv5 A plane)
    sortpool_k<<<GG, NPG>>>(p_x4, p_sel);
    gather_k<<<GG*KTOP, 256>>>(p_sel);

    // conv5: [15840,800]x[800,128] + relu
    gemm2_k<<<dim3(1, (GG*KTOP + TBM - 1)/TBM), 256, SM_GEMM2>>>(p_xselp, p_w5p, bc5, p_y5,
                                                                  GG*KTOP, KP5, 128, 1, 0, KP5);
    maxpool_k<<<(GG*15*128 + 255)/256, 256>>>(p_y5);
    // conv6: strided-row remap, [5808,640]x[640,256] + relu
    gemm2_k<<<dim3(EMB/TBN, (GG*11 + TBM - 1)/TBM), 256, SM_GEMM2>>>(p_y2p, p_w6p, bc6, p_y3,
                                                                      GG*11, 640, EMB, 1, 1, 0);
    embre_k<<<GG*11, 256>>>(p_y3, p_emb);
    dense1_k<<<dim3(BATCH, 4), 256>>>(p_emb, Wc1, bc1, p_hd);
    dense2_k<<<2, 256>>>(p_hd, Wc2, bc2, out);
}

// round 7
// speedup vs baseline: 1.3372x; 1.0100x over previous
#include <cuda_runtime.h>
#include <cuda_bf16.h>
#include <cstdint>
#include <math.h>

#define FEAT_IN 64
#define EMB     256
#define KTOP    30
#define BATCH   48
#define NGR     11
#define GG      528
#define NPG     192
#define EPG     384
#define NN      (GG*NPG)   // 101376
#define EE      (GG*EPG)   // 202752
#define DD      769
#define KP5     800        // conv5 K padded to 32
#define DENSE   2816
#define KIN     (NGR*DENSE)

// ================= scratch =================
__device__ float g_dis[NN];
__device__ float g_h[(long)NN*EMB];
__device__ float g_x1[(long)NN*EMB];
__device__ float g_x2[(long)NN*EMB];
__device__ float g_x3[(long)NN*EMB];
__device__ float g_h4[NN];
__device__ float g_x4[NN];
__device__ int   g_sel[GG*KTOP];
__device__ float g_y5[(long)GG*KTOP*128];
__device__ float g_y3[(long)GG*11*EMB];
__device__ float g_emb[(long)BATCH*KIN];
__device__ float g_hd[BATCH*EMB];
// pre-split tf32 (hi,lo) planes
__device__ uint2 g_sx[(long)NN*FEAT_IN];        // x split (layer1 A)
__device__ uint2 g_s[(long)NN*EMB];             // x1/x2 split (layer2/3 A)
__device__ uint2 g_wb[3][EMB*EMB];              // W1..W3 planes [K][256]
__device__ uint2 g_w5p[(long)KP5*128];          // conv5 B plane [800][128]
__device__ uint2 g_w6p[(long)640*EMB];          // conv6 B plane [640][256]
__device__ uint2 g_xselp[(long)GG*KTOP*KP5];    // conv5 A plane [15840][800]
__device__ uint2 g_y2p[(long)GG*15*128];        // conv6 A plane (remapped rows)

// ================= helpers =================
__device__ __forceinline__ uint32_t smem_u32(const void* p) {
    uint32_t a;
    asm("{ .reg .u64 t; cvta.to.shared.u64 t, %1; cvt.u32.u64 %0, t; }" : "=r"(a) : "l"(p));
    return a;
}
__device__ __forceinline__ uint2 tf32_split(float v) {
    uint32_t hi;
    asm("cvt.rna.tf32.f32 %0, %1;" : "=r"(hi) : "f"(v));
    float r = v - __uint_as_float(hi);
    uint32_t lo;
    asm("cvt.rna.tf32.f32 %0, %1;" : "=r"(lo) : "f"(r));
    return make_uint2(hi, lo);
}
__device__ __forceinline__ void mma_tf32(float* d, uint32_t a0, uint32_t a1,
                                         uint32_t a2, uint32_t a3,
                                         uint32_t b0, uint32_t b1) {
    asm volatile("mma.sync.aligned.m16n8k8.row.col.f32.tf32.tf32.f32 "
        "{%0,%1,%2,%3}, {%4,%5,%6,%7}, {%8,%9}, {%0,%1,%2,%3};"
        : "+f"(d[0]), "+f"(d[1]), "+f"(d[2]), "+f"(d[3])
        : "r"(a0), "r"(a1), "r"(a2), "r"(a3), "r"(b0), "r"(b1));
}
__device__ __forceinline__ void cp16(uint32_t dst, const void* src, bool valid) {
    int sz = valid ? 16 : 0;
    asm volatile("cp.async.cg.shared.global [%0], [%1], 16, %2;"
                 :: "r"(dst), "l"(src), "r"(sz));
}
#define CP_COMMIT() asm volatile("cp.async.commit_group;" ::: "memory")
#define CP_WAIT0()  asm volatile("cp.async.wait_group 0;" ::: "memory")
#define CP_WAIT1()  asm volatile("cp.async.wait_group 1;" ::: "memory")

// ================= double-buffered TF32 GEMM (128 thr, 2 CTAs/SM) =================
// C[M,Nc] = A[M,K] @ B[K,Nc], operands pre-split tf32 (hi,lo) uint2 planes.
// CTA tile 128x64, BK=32, 4 warps (2Mx2N), warp tile 64x32, 3 mma products.
#define TBM 128
#define TBN 64
#define TBK 32
#define AS_STR 36       // uint2 stride (288 B rows)
#define BS_STR 68       // uint2 stride (544 B rows)
#define ST_A_B (TBM*AS_STR*8)            // 36864
#define ST_B_B (TBK*BS_STR*8)            // 17408
#define STAGE_B (ST_A_B + ST_B_B)        // 54272
#define SM_GEMM2 (2*STAGE_B + 512)       // 109056 + rowbase

__global__ __launch_bounds__(128, 2)
void gemm2_k(const uint2* __restrict__ A, const uint2* __restrict__ B,
             const float* __restrict__ bias, float* __restrict__ C,
             int M, int K, int Nc, int relu, int mode, int ldA)
{
    extern __shared__ char smem_raw[];
    int* rowbase = (int*)(smem_raw + 2*STAGE_B);
    uint32_t sbase = smem_u32(smem_raw);

    int tid = threadIdx.x;
    int w   = tid >> 5, lane = tid & 31;
    int wm  = w & 1, wn = w >> 1;          // 2 x 2 warp grid
    int grp = lane >> 2, qd = lane & 3;
    int row0 = blockIdx.y * TBM;
    int col0 = blockIdx.x * TBN;

    if (tid < TBM) {
        int gm = row0 + tid;
        int base = -1;
        if (gm < M) base = (mode == 0) ? gm * ldA : 128 * (gm + 4*(gm/11));
        rowbase[tid] = base;
    }
    __syncthreads();

    float acc[4][4][4];
    #pragma unroll
    for (int i = 0; i < 4; i++)
        #pragma unroll
        for (int j = 0; j < 4; j++)
            #pragma unroll
            for (int q = 0; q < 4; q++) acc[i][j][q] = 0.f;

    int chunks = K / TBK;

    #define ISSUE(cidx, stg) do {                                               \
        int _k0 = (cidx) * TBK;                                                 \
        uint32_t _st = sbase + (stg) * STAGE_B;                                 \
        _Pragma("unroll")                                                       \
        for (int q = 0; q < 16; q++) {                                          \
            int f = q*128 + tid;                                                \
            int m = f >> 4, u = f & 15;                                         \
            int rb = rowbase[m];                                                \
            uint32_t dst = _st + m*288 + u*16;                                  \
            const void* srcp = (rb >= 0) ? (const void*)(A + (long)rb + _k0 + u*2) \
                                         : (const void*)A;                      \
            cp16(dst, srcp, rb >= 0);                                           \
        }                                                                       \
        _Pragma("unroll")                                                       \
        for (int q = 0; q < 8; q++) {                                           \
            int f = q*128 + tid;                                                \
            int kk = f >> 5, u = f & 31;                                        \
            uint32_t dst = _st + ST_A_B + kk*544 + u*16;                        \
            cp16(dst, (const void*)(B + (long)(_k0 + kk)*Nc + col0 + u*2), true);\
        }                                                                       \
    } while (0)

    ISSUE(0, 0);
    CP_COMMIT();

    for (int c = 0; c < chunks; c++) {
        if (c + 1 < chunks) {
            ISSUE(c + 1, (c + 1) & 1);
            CP_COMMIT();
            CP_WAIT1();
        } else {
            CP_WAIT0();
        }
        __syncthreads();

        const uint2* As = (const uint2*)(smem_raw + (c & 1) * STAGE_B);
        const uint2* Bs = (const uint2*)(smem_raw + (c & 1) * STAGE_B + ST_A_B);

        #pragma unroll
        for (int ks = 0; ks < 4; ks++) {
            int kb = ks * 8;
            uint2 af[4][4];
            #pragma unroll
            for (int mi = 0; mi < 4; mi++) {
                int r = wm*64 + mi*16 + grp;
                af[mi][0] = As[(r   )*AS_STR + kb + qd    ];
                af[mi][1] = As[(r+8 )*AS_STR + kb + qd    ];
                af[mi][2] = As[(r   )*AS_STR + kb + qd + 4];
                af[mi][3] = As[(r+8 )*AS_STR + kb + qd + 4];
            }
            uint2 bf[4][2];
            #pragma unroll
            for (int ni = 0; ni < 4; ni++) {
                int n = wn*32 + ni*8 + grp;
                bf[ni][0] = Bs[(kb + qd    )*BS_STR + n];
                bf[ni][1] = Bs[(kb + qd + 4)*BS_STR + n];
            }
            #pragma unroll
            for (int mi = 0; mi < 4; mi++)
                #pragma unroll
                for (int ni = 0; ni < 4; ni++) {
                    float* d = acc[mi][ni];
                    mma_tf32(d, af[mi][0].y, af[mi][1].y, af[mi][2].y, af[mi][3].y,
                             bf[ni][0].x, bf[ni][1].x);
                    mma_tf32(d, af[mi][0].x, af[mi][1].x, af[mi][2].x, af[mi][3].x,
                             bf[ni][0].y, bf[ni][1].y);
                    mma_tf32(d, af[mi][0].x, af[mi][1].x, af[mi][2].x, af[mi][3].x,
                             bf[ni][0].x, bf[ni][1].x);
                }
        }
        __syncthreads();
    }
    #undef ISSUE

    // ---- epilogue ----
    #pragma unroll
    for (int mi = 0; mi < 4; mi++) {
        int r0 = row0 + wm*64 + mi*16 + grp;
        #pragma unroll
        for (int ni = 0; ni < 4; ni++) {
            int cc = col0 + wn*32 + ni*8 + 2*qd;
            float b0v = bias ? bias[cc] : 0.f;
            float b1v = bias ? bias[cc+1] : 0.f;
            float v0 = acc[mi][ni][0] + b0v, v1 = acc[mi][ni][1] + b1v;
            float v2 = acc[mi][ni][2] + b0v, v3 = acc[mi][ni][3] + b1v;
            if (relu) { v0 = fmaxf(v0,0.f); v1 = fmaxf(v1,0.f);
                        v2 = fmaxf(v2,0.f); v3 = fmaxf(v3,0.f); }
            if (r0 < M)     *(float2*)(C + (long)r0*Nc + cc)     = make_float2(v0, v1);
            if (r0+8 < M)   *(float2*)(C + (long)(r0+8)*Nc + cc) = make_float2(v2, v3);
        }
    }
}

// ================= degree =================
__global__ void deg_init_k() { int i = blockIdx.x*256+threadIdx.x; if (i < NN) g_dis[i] = 1.0f; }
__global__ void deg_cnt_k(const int* __restrict__ dst) {
    int e = blockIdx.x*256+threadIdx.x; if (e < EE) atomicAdd(&g_dis[dst[e]], 1.0f);
}
__global__ void deg_fin_k() { int i = blockIdx.x*256+threadIdx.x; if (i < NN) g_dis[i] = rsqrtf(g_dis[i]); }

// ================= input / weight split kernels =================
__global__ void splitx_k(const float* __restrict__ x) {
    long i = (long)blockIdx.x*256 + threadIdx.x;
    if (i < (long)NN*FEAT_IN) g_sx[i] = tf32_split(x[i]);
}
__global__ void wsplit_k(const float* __restrict__ W, uint2* __restrict__ o, int n) {
    int i = blockIdx.x*256 + threadIdx.x;
    if (i < n) o[i] = tf32_split(W[i]);
}
__global__ void tw5_k(const float* __restrict__ w5) {
    int i = blockIdx.x*256 + threadIdx.x;          // over 800*128
    if (i >= KP5*128) return;
    int d = i >> 7, oc = i & 127;
    float v = (d < DD) ? w5[oc*DD + d] : 0.f;
    g_w5p[i] = tf32_split(v);
}
__global__ void tw6_k(const float* __restrict__ w6) {
    int i = blockIdx.x*256 + threadIdx.x;          // over 640*256
    if (i >= 640*EMB) return;
    int kr = i >> 8, oc = i & 255;
    int j = kr >> 7, ic = kr & 127;
    g_w6p[i] = tf32_split(w6[oc*640 + ic*5 + j]);
}

// ================= GCN aggregation (+fused split) =================
#define CCH 64
__global__ void gcn_agg_k(const float* __restrict__ h, const int* __restrict__ src,
                          const int* __restrict__ dst, const float* __restrict__ bias,
                          float* __restrict__ out, uint2* __restrict__ sp)
{
    extern __shared__ float sm[];
    float* hs   = sm;
    float* as   = hs + NPG*CCH;
    float* diss = as + NPG*CCH;
    int*  srcl  = (int*)(diss + NPG);
    int*  dstl  = srcl + EPG;
    int g = blockIdx.x >> 2;
    int chunk = blockIdx.x & 3;
    int tid = threadIdx.x;
    int c0 = chunk * CCH;

    for (int i = tid; i < NPG; i += 256) diss[i] = g_dis[g*NPG + i];
    for (int e = tid; e < EPG; e += 256) {
        srcl[e] = src[g*EPG + e] - g*NPG;
        dstl[e] = dst[g*EPG + e] - g*NPG;
    }
    __syncthreads();
    for (int f = tid; f < NPG*CCH; f += 256) {
        int node = f >> 6, c = f & 63;
        float v = h[(long)(g*NPG + node)*EMB + c0 + c];
        hs[f] = v;
        float d = diss[node];
        as[f] = v * d * d;
    }
    __syncthreads();
    int esub = tid >> 6, c = tid & 63;
    for (int e0 = 0; e0 < EPG; e0 += 4) {
        int e = e0 + esub;
        int s = srcl[e], d = dstl[e];
        float coef = diss[s] * diss[d];
        atomicAdd(&as[d*CCH + c], hs[s*CCH + c] * coef);
    }
    __syncthreads();
    for (int f = tid; f < NPG*CCH; f += 256) {
        int node = f >> 6, cc = f & 63;
        long o = (long)(g*NPG + node)*EMB + c0 + cc;
        float v = tanhf(as[f] + bias[c0 + cc]);
        out[o] = v;
        if (sp) sp[o] = tf32_split(v);
    }
}

// ================= layer 4 =================
__global__ void gemv4_k(const float* __restrict__ x3, const float* __restrict__ W4,
                        float* __restrict__ h4)
{
    int warp = (blockIdx.x*blockDim.x + threadIdx.x) >> 5;
    int lane = threadIdx.x & 31;
    if (warp >= NN) return;
    const float* row = x3 + (long)warp*EMB;
    float s = 0.f;
    #pragma unroll 4
    for (int c = lane; c < EMB; c += 32) s += row[c] * W4[c];
    #pragma unroll
    for (int o = 16; o > 0; o >>= 1) s += __shfl_down_sync(0xffffffffu, s, o);
    if (lane == 0) h4[warp] = s;
}
__global__ void gcn4_k(const float* __restrict__ h4, const int* __restrict__ src,
                       const int* __restrict__ dst, const float* __restrict__ b4,
                       float* __restrict__ x4out)
{
    __shared__ float hv[NPG], av[NPG], dv[NPG];
    int g = blockIdx.x, tid = threadIdx.x;
    for (int i = tid; i < NPG; i += 256) {
        float v = h4[g*NPG + i];
        float d = g_dis[g*NPG + i];
        hv[i] = v; dv[i] = d; av[i] = v*d*d;
    }
    __syncthreads();
    for (int e = tid; e < EPG; e += 256) {
        int s = src[g*EPG + e] - g*NPG;
        int d = dst[g*EPG + e] - g*NPG;
        atomicAdd(&av[d], hv[s]*dv[s]*dv[d]);
    }
    __syncthreads();
    float bb = b4[0];
    for (int i = tid; i < NPG; i += 256)
        x4out[g*NPG + i] = tanhf(av[i] + bb);
}

// ================= sort pool / gather (fused split to conv5 A plane) =================
__global__ void sortpool_k(const float* __restrict__ x4, int* __restrict__ sel)
{
    __shared__ float v[NPG];
    int g = blockIdx.x, t = threadIdx.x;
    v[t] = x4[g*NPG + t];
    __syncthreads();
    float mv = v[t];
    int rank = 0;
    for (int j = 0; j < NPG; j++) {
        float o = v[j];
        rank += (o > mv) || (o == mv && j < t);
    }
    if (rank < KTOP) sel[g*KTOP + rank] = t;
}
__global__ void gather_k(const int* __restrict__ sel)
{
    int r = blockIdx.x;                 // 0..G*K-1
    int g = r / KTOP;
    long node = (long)g*NPG + sel[r];
    uint2* o = g_xselp + (long)r*KP5;
    int t = threadIdx.x;                // 256
    o[t]        = tf32_split(g_x1[node*EMB + t]);
    o[256 + t]  = tf32_split(g_x2[node*EMB + t]);
    o[512 + t]  = tf32_split(g_x3[node*EMB + t]);
    if (t == 0) o[768] = tf32_split(g_x4[node]);
    if (t < KP5 - DD) o[DD + t] = make_uint2(0u, 0u);
}

// ================= maxpool (fused split to conv6 A plane) =================
__global__ void maxpool_k(const float* __restrict__ y5)
{
    int idx = blockIdx.x*blockDim.x + threadIdx.x;
    if (idx >= GG*15*128) return;
    int oc = idx & 127;
    int p  = (idx >> 7) % 15;
    int g  = idx / (15*128);
    float a = y5[((long)g*KTOP + 2*p)*128 + oc];
    float b = y5[((long)g*KTOP + 2*p + 1)*128 + oc];
    g_y2p[idx] = tf32_split(fmaxf(a, b));
}

// ================= reshape / dense =================
__global__ void embre_k(const float* __restrict__ y3, float* __restrict__ emb)
{
    int r = blockIdx.x;
    int oc = threadIdx.x;
    int g = r / 11, t = r % 11;
    int b = g / NGR, ng = g % NGR;
    emb[(long)b*KIN + ng*DENSE + oc*11 + t] = y3[(long)r*EMB + oc];
}
__global__ void dense1_k(const float* __restrict__ emb, const float* __restrict__ Wc1,
                         const float* __restrict__ bc1, float* __restrict__ hd)
{
    int b = blockIdx.x, ch = blockIdx.y;
    int tid = threadIdx.x;
    int oc = ch*64 + (tid & 63);
    int s = tid >> 6;
    const int SL = KIN / 4;
    const float* arow = emb + (long)b*KIN;
    float acc = 0.f;
    int i0 = s*SL, i1 = i0 + SL;
    #pragma unroll 4
    for (int i = i0; i < i1; i++) acc += arow[i] * Wc1[(long)i*EMB + oc];
    __shared__ float red[256];
    red[tid] = acc;
    __syncthreads();
    if (s == 0) {
        float v = red[tid] + red[tid+64] + red[tid+128] + red[tid+192] + bc1[oc];
        hd[b*EMB + oc] = fmaxf(v, 0.f);
    }
}
__global__ void dense2_k(const float* __restrict__ hd, const float* __restrict__ Wc2,
                         const float* __restrict__ bc2, float* __restrict__ out)
{
    int t = blockIdx.x*blockDim.x + threadIdx.x;
    if (t >= BATCH*10) return;
    int b = t / 10, o = t % 10;
    float s = bc2[o];
    #pragma unroll 8
    for (int k = 0; k < EMB; k++) s += hd[b*EMB + k] * Wc2[k*10 + o];
    out[t] = s;
}

// ================= launch =================
extern "C" void kernel_launch(void* const* d_in, const int* in_sizes, int n_in,
                              void* d_out, int out_size)
{
    const float* x   = (const float*)d_in[0];
    const int*   src = (const int*)d_in[1];
    const int*   dst = (const int*)d_in[2];
    const float* W1  = (const float*)d_in[3];
    const float* b1  = (const float*)d_in[4];
    const float* W2  = (const float*)d_in[5];
    const float* b2  = (const float*)d_in[6];
    const float* W3  = (const float*)d_in[7];
    const float* b3  = (const float*)d_in[8];
    const float* W4  = (const float*)d_in[9];
    const float* b4  = (const float*)d_in[10];
    const float* w5  = (const float*)d_in[11];
    const float* bc5 = (const float*)d_in[12];
    const float* w6  = (const float*)d_in[13];
    const float* bc6 = (const float*)d_in[14];
    const float* Wc1 = (const float*)d_in[15];
    const float* bc1 = (const float*)d_in[16];
    const float* Wc2 = (const float*)d_in[17];
    const float* bc2 = (const float*)d_in[18];
    float* out = (float*)d_out;

    float *p_h, *p_x1, *p_x2, *p_x3, *p_h4, *p_x4, *p_y5, *p_y3, *p_emb, *p_hd;
    int* p_sel;
    uint2 *p_sx, *p_s, *p_wb, *p_w5p, *p_w6p, *p_xselp, *p_y2p;
    cudaGetSymbolAddress((void**)&p_h,    g_h);
    cudaGetSymbolAddress((void**)&p_x1,   g_x1);
    cudaGetSymbolAddress((void**)&p_x2,   g_x2);
    cudaGetSymbolAddress((void**)&p_x3,   g_x3);
    cudaGetSymbolAddress((void**)&p_h4,   g_h4);
    cudaGetSymbolAddress((void**)&p_x4,   g_x4);
    cudaGetSymbolAddress((void**)&p_sel,  g_sel);
    cudaGetSymbolAddress((void**)&p_y5,   g_y5);
    cudaGetSymbolAddress((void**)&p_y3,   g_y3);
    cudaGetSymbolAddress((void**)&p_emb,  g_emb);
    cudaGetSymbolAddress((void**)&p_hd,   g_hd);
    cudaGetSymbolAddress((void**)&p_sx,   g_sx);
    cudaGetSymbolAddress((void**)&p_s,    g_s);
    cudaGetSymbolAddress((void**)&p_wb,   g_wb);
    cudaGetSymbolAddress((void**)&p_w5p,  g_w5p);
    cudaGetSymbolAddress((void**)&p_w6p,  g_w6p);
    cudaGetSymbolAddress((void**)&p_xselp,g_xselp);
    cudaGetSymbolAddress((void**)&p_y2p,  g_y2p);

    const size_t SMB = (size_t)(NPG*CCH*2 + NPG)*4 + (size_t)EPG*2*4;
    cudaFuncSetAttribute(gcn_agg_k, cudaFuncAttributeMaxDynamicSharedMemorySize, (int)SMB);
    cudaFuncSetAttribute(gemm2_k, cudaFuncAttributeMaxDynamicSharedMemorySize, SM_GEMM2);

    // -- launch order arranged so launch index 5 (ncu -s 5 -c 1) is gemm2_k --
    splitx_k<<<(int)(((long)NN*FEAT_IN+255)/256), 256>>>(x);                      // 0
    wsplit_k<<<(FEAT_IN*256+255)/256, 256>>>(W1, p_wb + 0L*EMB*EMB, FEAT_IN*256); // 1
    deg_init_k<<<(NN+255)/256, 256>>>();                                          // 2
    deg_cnt_k<<<(EE+255)/256, 256>>>(dst);                                        // 3
    deg_fin_k<<<(NN+255)/256, 256>>>();                                           // 4

    // layer 1 GEMM  (launch #5 -> profiled)
    gemm2_k<<<dim3(EMB/TBN, NN/TBM), 128, SM_GEMM2>>>(p_sx, p_wb + 0L*EMB*EMB, nullptr, p_h,
                                                       NN, FEAT_IN, EMB, 0, 0, FEAT_IN);
    gcn_agg_k<<<GG*4, 256, SMB>>>(p_h, src, dst, b1, p_x1, p_s);
    wsplit_k<<<(EMB*256+255)/256, 256>>>(W2, p_wb + 1L*EMB*EMB, EMB*256);
    gemm2_k<<<dim3(EMB/TBN, NN/TBM), 128, SM_GEMM2>>>(p_s, p_wb + 1L*EMB*EMB, nullptr, p_h,
                                                       NN, EMB, EMB, 0, 0, EMB);
    gcn_agg_k<<<GG*4, 256, SMB>>>(p_h, src, dst, b2, p_x2, p_s);
    wsplit_k<<<(EMB*256+255)/256, 256>>>(W3, p_wb + 2L*EMB*EMB, EMB*256);
    gemm2_k<<<dim3(EMB/TBN, NN/TBM), 128, SM_GEMM2>>>(p_s, p_wb + 2L*EMB*EMB, nullptr, p_h,
                                                       NN, EMB, EMB, 0, 0, EMB);
    gcn_agg_k<<<GG*4, 256, SMB>>>(p_h, src, dst, b3, p_x3, nullptr);
    // layer 4
    gemv4_k<<<(NN*32+255)/256, 256>>>(p_x3, W4, p_h4);
    gcn4_k<<<GG, 256>>>(p_h4, src, dst, b4, p_x4);

    // sort pooling + gather (writes split conv5 A plane)
    sortpool_k<<<GG, NPG>>>(p_x4, p_sel);
    gather_k<<<GG*KTOP, 256>>>(p_sel);

    // conv5: [15840,800]x[800,128] + relu
    tw5_k<<<(KP5*128+255)/256, 256>>>(w5);
    gemm2_k<<<dim3(128/TBN, (GG*KTOP + TBM - 1)/TBM), 128, SM_GEMM2>>>(p_xselp, p_w5p, bc5, p_y5,
                                                                        GG*KTOP, KP5, 128, 1, 0, KP5);
    maxpool_k<<<(GG*15*128 + 255)/256, 256>>>(p_y5);
    // conv6: strided-row remap, [5808,640]x[640,256] + relu
    tw6_k<<<(640*EMB+255)/256, 256>>>(w6);
    gemm2_k<<<dim3(EMB/TBN, (GG*11 + TBM - 1)/TBM), 128, SM_GEMM2>>>(p_y2p, p_w6p, bc6, p_y3,
                                                                      GG*11, 640, EMB, 1, 1, 0);
    embre_k<<<GG*11, 256>>>(p_y3, p_emb);
    dense1_k<<<dim3(BATCH, 4), 256>>>(p_emb, Wc1, bc1, p_hd);
    dense2_k<<<2, 256>>>(p_hd, Wc2, bc2, out);
}